// round 2
// baseline (speedup 1.0000x reference)
#include <cuda_runtime.h>

#define EPS 1e-12f

__global__ void microfacet_kernel(const float* __restrict__ in,
                                  const float* __restrict__ base_color,
                                  const float* __restrict__ eta_p,
                                  float* __restrict__ out,
                                  int n)
{
    int i = blockIdx.x * blockDim.x + threadIdx.x;
    if (i >= n) return;

    const float* p = in + (size_t)i * 9;
    float lx = p[0], ly = p[1], lz = p[2];
    float nx = p[3], ny = p[4], nz = p[5];
    float vx = p[6], vy = p[7], vz = p[8];

    float e = __ldg(eta_p);
    float bc0 = __ldg(base_color + 0);
    float bc1 = __ldg(base_color + 1);
    float bc2 = __ldg(base_color + 2);

    // half vector
    float hx = lx + vx, hy = ly + vy, hz = lz + vz;
    float hnorm = sqrtf(hx * hx + hy * hy + hz * hz);
    float inv = 1.0f / fmaxf(hnorm, EPS);
    hx *= inv; hy *= inv; hz *= inv;

    float nl = nx * lx + ny * ly + nz * lz;
    float nv = nx * vx + ny * vy + nz * vz;
    float vh = vx * hx + vy * hy + vz * hz;

    float d_term = 0.0f;
    float g_term = nl * nv;

    float c  = vh;
    float gg = e * e + c * c - 1.0f;
    float gs = sqrtf(fmaxf(gg, EPS));
    float a  = (gs - c) / (gs + c);
    float b  = (c * (gs + c) - 1.0f) / (c * (gs - c) + 1.0f);
    float fr = (gg > 0.0f) ? (0.5f * a * a * (1.0f + b * b)) : 1.0f;

    float denom = 4.0f * nl * nv;
    float scale = d_term * g_term * fr / denom;

    float* o = out + (size_t)i * 3;
    o[0] = bc0 * scale;
    o[1] = bc1 * scale;
    o[2] = bc2 * scale;
}

extern "C" void kernel_launch(void* const* d_in, const int* in_sizes, int n_in,
                              void* d_out, int out_size)
{
    const float* in         = (const float*)d_in[0];
    const float* base_color = (const float*)d_in[1];
    // d_in[2] is alpha (unused by the reference math)
    const float* eta        = (const float*)d_in[3];
    float* out = (float*)d_out;

    int n = in_sizes[0] / 9;
    int threads = 256;
    int blocks = (n + threads - 1) / threads;
    microfacet_kernel<<<blocks, threads>>>(in, base_color, eta, out, n);
}